// round 2
// baseline (speedup 1.0000x reference)
#include <cuda_runtime.h>
#include <cstdint>

#define BB 8
#define LL 256
#define DD 512
#define HH 512
#define NTOT (LL*BB*LL)          // 524288

// Scratch: transposed projections dl_t[b][h][i], dr_t[b][h][i]
__device__ float g_dlt[BB*HH*LL];
__device__ float g_drt[BB*HH*LL];

// ---------------------------------------------------------------------------
// Kernel 1: fused dual GEMM.  dl_t[b,h,i] = sum_k enc[b,i,k]*Wl[k,h]
//                             dr_t[b,h,i] = sum_k enc[b,i,k]*Wr[k,h]
// Block: 64h x 64i tile for one b. 256 threads, 4x4(+4x4) per thread.
// ---------------------------------------------------------------------------
__global__ __launch_bounds__(256) void dual_gemm_kernel(
    const float* __restrict__ enc,
    const float* __restrict__ Wl,
    const float* __restrict__ Wr)
{
    const int b  = blockIdx.z;
    const int h0 = blockIdx.x * 64;
    const int i0 = blockIdx.y * 64;

    __shared__ float se[16][68];   // [k][i] (padded)
    __shared__ float swl[16][64];  // [k][h]
    __shared__ float swr[16][64];

    const int tid = threadIdx.x;
    const int tx  = tid & 15;      // h group
    const int ty  = tid >> 4;      // i group

    float accl[4][4];  // [c=h][a=i]
    float accr[4][4];
#pragma unroll
    for (int c = 0; c < 4; c++)
#pragma unroll
        for (int a = 0; a < 4; a++) { accl[c][a] = 0.f; accr[c][a] = 0.f; }

    for (int k0 = 0; k0 < DD; k0 += 16) {
        {
            int kk = tid >> 4;          // 0..15
            int hh = (tid & 15) << 2;   // 0..60
            const float4 vl = *(const float4*)&Wl[(k0 + kk) * HH + h0 + hh];
            const float4 vr = *(const float4*)&Wr[(k0 + kk) * HH + h0 + hh];
            *(float4*)&swl[kk][hh] = vl;
            *(float4*)&swr[kk][hh] = vr;
        }
        {
            int ii = tid >> 2;          // 0..63
            int kk = (tid & 3) << 2;    // 0,4,8,12
            const float4 v = *(const float4*)&enc[(b * LL + i0 + ii) * DD + k0 + kk];
            se[kk + 0][ii] = v.x;
            se[kk + 1][ii] = v.y;
            se[kk + 2][ii] = v.z;
            se[kk + 3][ii] = v.w;
        }
        __syncthreads();

#pragma unroll
        for (int kk = 0; kk < 16; kk++) {
            float ev[4], wlv[4], wrv[4];
            *(float4*)ev  = *(const float4*)&se[kk][ty << 2];
            *(float4*)wlv = *(const float4*)&swl[kk][tx << 2];
            *(float4*)wrv = *(const float4*)&swr[kk][tx << 2];
#pragma unroll
            for (int c = 0; c < 4; c++)
#pragma unroll
                for (int a = 0; a < 4; a++) {
                    accl[c][a] = fmaf(ev[a], wlv[c], accl[c][a]);
                    accr[c][a] = fmaf(ev[a], wrv[c], accr[c][a]);
                }
        }
        __syncthreads();
    }

#pragma unroll
    for (int c = 0; c < 4; c++) {
        const int h = h0 + (tx << 2) + c;
        const int base = (b * HH + h) * LL + i0 + (ty << 2);
        *(float4*)&g_dlt[base] = make_float4(accl[c][0], accl[c][1], accl[c][2], accl[c][3]);
        *(float4*)&g_drt[base] = make_float4(accr[c][0], accr[c][1], accr[c][2], accr[c][3]);
    }
}

// ---------------------------------------------------------------------------
// Threefry2x32, key (0, 42), PARTITIONABLE path (JAX >= 0.4.36 default):
// per element m, counter = uint64 linear index -> (hi, lo) = (0, m);
// output bits = out_lane0 ^ out_lane1.
// ---------------------------------------------------------------------------
__device__ __forceinline__ unsigned threefry_bits_partitionable(unsigned m)
{
    const unsigned k0 = 0u, k1 = 42u;
    const unsigned k2 = 0x1BD11BDAu ^ k0 ^ k1;
    unsigned x0 = 0u + k0;    // counts_hi = 0 (m < 2^32)
    unsigned x1 = m  + k1;    // counts_lo = m
#define TF_RND(r) { x0 += x1; x1 = __funnelshift_l(x1, x1, r); x1 ^= x0; }
    TF_RND(13) TF_RND(15) TF_RND(26) TF_RND(6)   x0 += k1; x1 += k2 + 1u;
    TF_RND(17) TF_RND(29) TF_RND(16) TF_RND(24)  x0 += k2; x1 += k0 + 2u;
    TF_RND(13) TF_RND(15) TF_RND(26) TF_RND(6)   x0 += k0; x1 += k1 + 3u;
    TF_RND(17) TF_RND(29) TF_RND(16) TF_RND(24)  x0 += k1; x1 += k2 + 4u;
    TF_RND(13) TF_RND(15) TF_RND(26) TF_RND(6)   x0 += k2; x1 += k0 + 5u;
#undef TF_RND
    return x0 ^ x1;
}

__device__ __forceinline__ float tanh_fast(float x)
{
    float y;
    asm("tanh.approx.f32 %0, %1;" : "=f"(y) : "f"(x));
    return y;
}

// ---------------------------------------------------------------------------
// Kernel 2: biaffine + mask + sigmoid/entropy/bernoulli epilogue.
// Block: 64i x 64j for one b. 256 threads, 4x4 per thread.
// out = [samples | mask_scores | entropy], each [L,B,L] flattened, float32.
// ---------------------------------------------------------------------------
__global__ __launch_bounds__(256) void biaffine_kernel(
    const float* __restrict__ U,
    const float* __restrict__ logit_bias,
    float* __restrict__ out)
{
    const int b  = blockIdx.z;
    const int i0 = blockIdx.y * 64;
    const int j0 = blockIdx.x * 64;

    __shared__ float sl[32][64];   // [h][i]
    __shared__ float sr[32][64];   // [h][j]
    __shared__ float su[32];

    const int tid = threadIdx.x;
    const int tx  = tid & 15;      // j group
    const int ty  = tid >> 4;      // i group

    float acc[4][4];               // [a=i][c=j]
#pragma unroll
    for (int a = 0; a < 4; a++)
#pragma unroll
        for (int c = 0; c < 4; c++) acc[a][c] = 0.f;

    for (int h0 = 0; h0 < HH; h0 += 32) {
#pragma unroll
        for (int q = 0; q < 2; q++) {
            int idx = tid + q * 256;        // 0..511
            int hk  = idx >> 4;             // 0..31
            int col = (idx & 15) << 2;      // 0..60
            *(float4*)&sl[hk][col] = *(const float4*)&g_dlt[(b * HH + h0 + hk) * LL + i0 + col];
            *(float4*)&sr[hk][col] = *(const float4*)&g_drt[(b * HH + h0 + hk) * LL + j0 + col];
        }
        if (tid < 32) su[tid] = U[h0 + tid];
        __syncthreads();

#pragma unroll
        for (int hk = 0; hk < 32; hk++) {
            float dl[4], dr[4];
            *(float4*)dl = *(const float4*)&sl[hk][ty << 2];
            *(float4*)dr = *(const float4*)&sr[hk][tx << 2];
            const float u = su[hk];
#pragma unroll
            for (int a = 0; a < 4; a++)
#pragma unroll
                for (int c = 0; c < 4; c++)
                    acc[a][c] = fmaf(u, tanh_fast(dl[a] + dr[c]), acc[a][c]);
        }
        __syncthreads();
    }

    const float lb = logit_bias[0];

#pragma unroll
    for (int a = 0; a < 4; a++) {
#pragma unroll
        for (int c = 0; c < 4; c++) {
            const int i = i0 + (ty << 2) + a;
            const int j = j0 + (tx << 2) + c;
            float x = acc[a][c] + lb;
            if (i == j) x -= 1e8f;

            const int m = i * (BB * LL) + b * LL + j;   // [L,B,L] flat index

            // mask_scores
            out[NTOT + m] = x;

            // p = sigmoid(x)
            const float p = 1.0f / (1.0f + expf(-x));

            // entropy = p*softplus(-x) + (1-p)*softplus(x)
            const float e  = expf(-fabsf(x));
            const float l1 = log1pf(e);
            const float sp_pos = fmaxf(x, 0.f) + l1;   // softplus(x)
            const float sp_neg = fmaxf(-x, 0.f) + l1;  // softplus(-x)
            out[2 * NTOT + m] = p * sp_neg + (1.0f - p) * sp_pos;

            // bernoulli sample, JAX partitionable threefry (key=42)
            const unsigned bits = threefry_bits_partitionable((unsigned)m);
            const float u01 = __uint_as_float((bits >> 9) | 0x3f800000u) - 1.0f;
            out[m] = (u01 < p) ? 1.0f : 0.0f;
        }
    }
}

// ---------------------------------------------------------------------------
extern "C" void kernel_launch(void* const* d_in, const int* in_sizes, int n_in,
                              void* d_out, int out_size)
{
    const float* enc  = (const float*)d_in[0];
    const float* Wl   = (const float*)d_in[1];
    const float* Wr   = (const float*)d_in[2];
    const float* U    = (const float*)d_in[3];
    const float* bias = (const float*)d_in[4];
    float* out = (float*)d_out;

    dim3 g1(HH / 64, LL / 64, BB);   // 8 x 4 x 8
    dual_gemm_kernel<<<g1, 256>>>(enc, Wl, Wr);

    dim3 g2(LL / 64, LL / 64, BB);   // 4 x 4 x 8
    biaffine_kernel<<<g2, 256>>>(U, bias, out);
}

// round 3
// speedup vs baseline: 1.0512x; 1.0512x over previous
#include <cuda_runtime.h>
#include <cstdint>

#define BB 8
#define LL 256
#define DD 512
#define HH 512
#define NTOT (LL*BB*LL)          // 524288

// Scratch: transposed projections dl_t[b][h][i], dr_t[b][h][i]
__device__ float g_dlt[BB*HH*LL];
__device__ float g_drt[BB*HH*LL];

// ---------------------------------------------------------------------------
// Kernel 1: fused dual GEMM.  dl_t[b,h,i] = sum_k enc[b,i,k]*Wl[k,h]
//                             dr_t[b,h,i] = sum_k enc[b,i,k]*Wr[k,h]
// Block: 64h x 64i tile for one b. 256 threads, 4x4(+4x4) per thread.
// ---------------------------------------------------------------------------
__global__ __launch_bounds__(256) void dual_gemm_kernel(
    const float* __restrict__ enc,
    const float* __restrict__ Wl,
    const float* __restrict__ Wr)
{
    const int b  = blockIdx.z;
    const int h0 = blockIdx.x * 64;
    const int i0 = blockIdx.y * 64;

    __shared__ float se[16][68];   // [k][i] (padded)
    __shared__ float swl[16][64];  // [k][h]
    __shared__ float swr[16][64];

    const int tid = threadIdx.x;
    const int tx  = tid & 15;      // h group
    const int ty  = tid >> 4;      // i group

    float accl[4][4];  // [c=h][a=i]
    float accr[4][4];
#pragma unroll
    for (int c = 0; c < 4; c++)
#pragma unroll
        for (int a = 0; a < 4; a++) { accl[c][a] = 0.f; accr[c][a] = 0.f; }

    for (int k0 = 0; k0 < DD; k0 += 16) {
        {
            int kk = tid >> 4;          // 0..15
            int hh = (tid & 15) << 2;   // 0..60
            const float4 vl = *(const float4*)&Wl[(k0 + kk) * HH + h0 + hh];
            const float4 vr = *(const float4*)&Wr[(k0 + kk) * HH + h0 + hh];
            *(float4*)&swl[kk][hh] = vl;
            *(float4*)&swr[kk][hh] = vr;
        }
        {
            int ii = tid >> 2;          // 0..63
            int kk = (tid & 3) << 2;    // 0,4,8,12
            const float4 v = *(const float4*)&enc[(b * LL + i0 + ii) * DD + k0 + kk];
            se[kk + 0][ii] = v.x;
            se[kk + 1][ii] = v.y;
            se[kk + 2][ii] = v.z;
            se[kk + 3][ii] = v.w;
        }
        __syncthreads();

#pragma unroll
        for (int kk = 0; kk < 16; kk++) {
            float ev[4], wlv[4], wrv[4];
            *(float4*)ev  = *(const float4*)&se[kk][ty << 2];
            *(float4*)wlv = *(const float4*)&swl[kk][tx << 2];
            *(float4*)wrv = *(const float4*)&swr[kk][tx << 2];
#pragma unroll
            for (int c = 0; c < 4; c++)
#pragma unroll
                for (int a = 0; a < 4; a++) {
                    accl[c][a] = fmaf(ev[a], wlv[c], accl[c][a]);
                    accr[c][a] = fmaf(ev[a], wrv[c], accr[c][a]);
                }
        }
        __syncthreads();
    }

#pragma unroll
    for (int c = 0; c < 4; c++) {
        const int h = h0 + (tx << 2) + c;
        const int base = (b * HH + h) * LL + i0 + (ty << 2);
        *(float4*)&g_dlt[base] = make_float4(accl[c][0], accl[c][1], accl[c][2], accl[c][3]);
        *(float4*)&g_drt[base] = make_float4(accr[c][0], accr[c][1], accr[c][2], accr[c][3]);
    }
}

// ---------------------------------------------------------------------------
// Threefry2x32, key (0, 42), partitionable path: counter = (0, m),
// output bits = lane0 ^ lane1.
// ---------------------------------------------------------------------------
__device__ __forceinline__ unsigned threefry_bits_partitionable(unsigned m)
{
    const unsigned k0 = 0u, k1 = 42u;
    const unsigned k2 = 0x1BD11BDAu ^ k0 ^ k1;
    unsigned x0 = 0u + k0;
    unsigned x1 = m  + k1;
#define TF_RND(r) { x0 += x1; x1 = __funnelshift_l(x1, x1, r); x1 ^= x0; }
    TF_RND(13) TF_RND(15) TF_RND(26) TF_RND(6)   x0 += k1; x1 += k2 + 1u;
    TF_RND(17) TF_RND(29) TF_RND(16) TF_RND(24)  x0 += k2; x1 += k0 + 2u;
    TF_RND(13) TF_RND(15) TF_RND(26) TF_RND(6)   x0 += k0; x1 += k1 + 3u;
    TF_RND(17) TF_RND(29) TF_RND(16) TF_RND(24)  x0 += k1; x1 += k2 + 4u;
    TF_RND(13) TF_RND(15) TF_RND(26) TF_RND(6)   x0 += k2; x1 += k0 + 5u;
#undef TF_RND
    return x0 ^ x1;
}

__device__ __forceinline__ float tanh_fast(float x)
{
    float y;
    asm("tanh.approx.f32 %0, %1;" : "=f"(y) : "f"(x));
    return y;
}

// ---------------------------------------------------------------------------
// Kernel 2: biaffine + epilogue. 64i x 32j tile per CTA -> 256 CTAs so all
// 148 SMs are busy and most hold 2 CTAs (16 warps) for latency hiding.
// 256 threads, 4i x 2j per thread.
// ---------------------------------------------------------------------------
__global__ __launch_bounds__(256) void biaffine_kernel(
    const float* __restrict__ U,
    const float* __restrict__ logit_bias,
    float* __restrict__ out)
{
    const int b  = blockIdx.z;
    const int i0 = blockIdx.y * 64;
    const int j0 = blockIdx.x * 32;

    __shared__ float sl[32][64];   // [h][i]
    __shared__ float sr[32][32];   // [h][j]
    __shared__ float su[32];

    const int tid = threadIdx.x;
    const int tx  = tid & 15;      // j group (2 j each)
    const int ty  = tid >> 4;      // i group (4 i each)

    float acc[4][2];               // [a=i][c=j]
#pragma unroll
    for (int a = 0; a < 4; a++)
#pragma unroll
        for (int c = 0; c < 2; c++) acc[a][c] = 0.f;

    for (int h0 = 0; h0 < HH; h0 += 32) {
        // sl: 32x64 floats = 512 float4 -> 2 per thread
#pragma unroll
        for (int q = 0; q < 2; q++) {
            int idx = tid + q * 256;        // 0..511
            int hk  = idx >> 4;             // 0..31
            int col = (idx & 15) << 2;      // 0..60
            *(float4*)&sl[hk][col] = *(const float4*)&g_dlt[(b * HH + h0 + hk) * LL + i0 + col];
        }
        // sr: 32x32 floats = 256 float4 -> 1 per thread
        {
            int hk  = tid >> 3;             // 0..31
            int col = (tid & 7) << 2;       // 0..28
            *(float4*)&sr[hk][col] = *(const float4*)&g_drt[(b * HH + h0 + hk) * LL + j0 + col];
        }
        if (tid < 32) su[tid] = U[h0 + tid];
        __syncthreads();

#pragma unroll
        for (int hk = 0; hk < 32; hk++) {
            float dl[4], dr[2];
            *(float4*)dl = *(const float4*)&sl[hk][ty << 2];
            *(float2*)dr = *(const float2*)&sr[hk][tx << 1];
            const float u = su[hk];
#pragma unroll
            for (int a = 0; a < 4; a++)
#pragma unroll
                for (int c = 0; c < 2; c++)
                    acc[a][c] = fmaf(u, tanh_fast(dl[a] + dr[c]), acc[a][c]);
        }
        __syncthreads();
    }

    const float lb = logit_bias[0];

#pragma unroll
    for (int a = 0; a < 4; a++) {
#pragma unroll
        for (int c = 0; c < 2; c++) {
            const int i = i0 + (ty << 2) + a;
            const int j = j0 + (tx << 1) + c;
            float x = acc[a][c] + lb;
            if (i == j) x -= 1e8f;

            const int m = i * (BB * LL) + b * LL + j;   // [L,B,L] flat index

            // mask_scores
            out[NTOT + m] = x;

            // p = sigmoid(x)
            const float p = 1.0f / (1.0f + expf(-x));

            // entropy = p*softplus(-x) + (1-p)*softplus(x)
            const float e  = expf(-fabsf(x));
            const float l1 = log1pf(e);
            const float sp_pos = fmaxf(x, 0.f) + l1;   // softplus(x)
            const float sp_neg = fmaxf(-x, 0.f) + l1;  // softplus(-x)
            out[2 * NTOT + m] = p * sp_neg + (1.0f - p) * sp_pos;

            // bernoulli sample, JAX partitionable threefry (key=42)
            const unsigned bits = threefry_bits_partitionable((unsigned)m);
            const float u01 = __uint_as_float((bits >> 9) | 0x3f800000u) - 1.0f;
            out[m] = (u01 < p) ? 1.0f : 0.0f;
        }
    }
}

// ---------------------------------------------------------------------------
extern "C" void kernel_launch(void* const* d_in, const int* in_sizes, int n_in,
                              void* d_out, int out_size)
{
    const float* enc  = (const float*)d_in[0];
    const float* Wl   = (const float*)d_in[1];
    const float* Wr   = (const float*)d_in[2];
    const float* U    = (const float*)d_in[3];
    const float* bias = (const float*)d_in[4];
    float* out = (float*)d_out;

    dim3 g1(HH / 64, LL / 64, BB);   // 8 x 4 x 8 = 256 CTAs
    dual_gemm_kernel<<<g1, 256>>>(enc, Wl, Wr);

    dim3 g2(LL / 32, LL / 64, BB);   // 8 x 4 x 8 = 256 CTAs
    biaffine_kernel<<<g2, 256>>>(U, bias, out);
}